// round 9
// baseline (speedup 1.0000x reference)
#include <cuda_runtime.h>
#include <math.h>

#define HH 640
#define WW 640
#define MHH 40
#define MWW 40
#define NC 8
#define NB 4
#define KPER 400

#define TILE 32
#define PLANE2 (34*35)                 // float2 units per plane
#define SMEM_BYTES (8*PLANE2*8)        // 76160: input planes only

typedef unsigned long long ull;

// scratch ping-pong buffers, interleaved float2 layout [b][c][H][W]
__device__ ull g_bufA[NB*NC*HH*WW];
__device__ ull g_bufB[NB*NC*HH*WW];
__device__ float g_bm[NB*MHH*MWW];
__device__ ulonglong2 g_wpack[4*576];     // packed weights staging

// weights in constant bank: [stage][((ci*3+kx)*8+co)*3+ky] = {wr,wr,-wi,wi}
__constant__ ulonglong2 c_wq[4*576];

// ---------------------------------------------------------------------------
// Pack weights: {wr, wr, -wi, wi} per (stage, ci, kx, co, ky), center zeroed.
// ---------------------------------------------------------------------------
__global__ void prep_weights(const float* __restrict__ wr_g,
                             const float* __restrict__ wi_g) {
    int j = blockIdx.x * blockDim.x + threadIdx.x;
    if (j >= 4*576) return;
    int s = j / 576, r = j % 576;
    int ky = r % 3, co = (r / 3) & 7, kx = (r / 24) % 3, ci = r / 72;
    int t = ky*3 + kx;
    float vr = 0.0f, vi = 0.0f;
    if (t != 4) {
        vr = wr_g[s*576 + (co*8 + ci)*9 + t];
        vi = wi_g[s*576 + (co*8 + ci)*9 + t];
    }
    float4 e; e.x = vr; e.y = vr; e.z = -vi; e.w = vi;
    ((float4*)g_wpack)[j] = e;
}

// ---------------------------------------------------------------------------
// Mask: sigmoid(s_b * w_eff), exact 400th-largest via binary search on float
// bits, binarize. One block per batch.
// ---------------------------------------------------------------------------
__global__ void mask_kernel(const float* __restrict__ my1,
                            const float* __restrict__ wmask,
                            float* __restrict__ out_bin, int write_bin) {
    __shared__ float s_sig[MHH*MWW];
    __shared__ int s_cnt;
    int b = blockIdx.x, tid = threadIdx.x;
    float sb = my1[b];
    for (int i = tid; i < MHH*MWW; i += blockDim.x) {
        int col = i % MWW;
        float wv = (col >= 18 && col < 23) ? 1e7f : wmask[i];
        s_sig[i] = 1.0f / (1.0f + expf(-sb * wv));
    }
    __syncthreads();
    unsigned lo = 0u, hi = 0x3F800001u;
    while (hi - lo > 1u) {
        unsigned mid = (lo + hi) >> 1;
        float t = __uint_as_float(mid);
        if (tid == 0) s_cnt = 0;
        __syncthreads();
        int c = 0;
        for (int i = tid; i < MHH*MWW; i += blockDim.x)
            c += (s_sig[i] >= t) ? 1 : 0;
        atomicAdd(&s_cnt, c);
        __syncthreads();
        int tot = s_cnt;
        __syncthreads();
        if (tot >= KPER) lo = mid; else hi = mid;
    }
    float thr = __uint_as_float(lo);
    for (int i = tid; i < MHH*MWW; i += blockDim.x) {
        float v = (s_sig[i] >= thr) ? 1.0f : 0.0f;
        g_bm[b*MHH*MWW + i] = v;
        if (write_bin) out_bin[b*MHH*MWW + i] = v;
    }
}

// ---------------------------------------------------------------------------
// Complex 3x3 conv (center zeroed) + data consistency.
// src/dst: interleaved float2 [b][c][H][W] (stored as ull).
// MASK_IN=1: src is raw x; zero where mask==0 on tile load; also writes
//            mask_adj to madj.
// 1024 threads: 32 cols x 16 row-groups x 2 co-groups.
// Thread: 2 rows x 4 couts -> 16 acc regs, 288 LDC.128 (halved vs 8-cout).
// Math: acc{r,i} += v{r,i}*{wr,wr} + vswap{i,r}*{-wi,wi}   (2 FFMA2/tap)
// ---------------------------------------------------------------------------
template<int MASK_IN>
__global__ void __launch_bounds__(1024, 1)
conv_kernel(const ull* __restrict__ src, ull* __restrict__ dst,
            float* __restrict__ madj, int stage_off) {
    extern __shared__ float smem[];
    ull* s_in = (ull*)smem;                 // 8 planes of 34x(35) float2

    const int tid = threadIdx.x;
    const int b  = blockIdx.z;
    const int x0 = blockIdx.x * TILE;
    const int y0 = blockIdx.y * TILE;

    // ---- load tile (halo 1, zero-padded) ----
    for (int idx = tid; idx < 34*34; idx += 1024) {
        int r = idx / 34, c = idx - r*34;
        int gh = y0 - 1 + r, gw = x0 - 1 + c;
        bool inb = (gh >= 0 && gh < HH && gw >= 0 && gw < WW);
        bool live = inb;
        if (MASK_IN) {
            float m = 0.0f;
            if (inb) m = g_bm[b*MHH*MWW + (gh % MHH)*MWW + (gw % MWW)];
            live = inb && (m != 0.0f);
        }
#pragma unroll
        for (int ci = 0; ci < 8; ci++) {
            ull v = 0ull;
            if (live) v = src[((b*NC + ci)*HH + gh)*WW + gw];
            s_in[ci*PLANE2 + r*35 + c] = v;
        }
    }
    __syncthreads();

    const int tx   = tid & 31;
    const int ty   = tid >> 5;        // 0..31
    const int rowg = ty & 15;
    const int cog  = ty >> 4;
    const int row0 = rowg * 2;
    const int co0  = cog * 4;

    ull acc[4][2];
#pragma unroll
    for (int c = 0; c < 4; c++) { acc[c][0] = 0ull; acc[c][1] = 0ull; }

#pragma unroll 1
    for (int ci = 0; ci < 8; ci++) {
        const ull* pb = s_in + ci*PLANE2 + row0*35 + tx;
#pragma unroll
        for (int kx = 0; kx < 3; kx++) {
            ull v64[4], vs64[4];
#pragma unroll
            for (int r = 0; r < 4; r++) {
                ull v = pb[r*35 + kx];
                v64[r] = v;
                float ar, ai;
                asm("mov.b64 {%0, %1}, %2;" : "=f"(ar), "=f"(ai) : "l"(v));
                asm("mov.b64 %0, {%1, %2};" : "=l"(vs64[r]) : "f"(ai), "f"(ar));
            }
            const int cb = stage_off + ((ci*3 + kx)*8 + co0)*3;
#pragma unroll
            for (int c = 0; c < 4; c++) {
                ulonglong2 wa = c_wq[cb + c*3 + 0];
                ulonglong2 wb = c_wq[cb + c*3 + 1];
                ulonglong2 wc = c_wq[cb + c*3 + 2];
                asm("fma.rn.f32x2 %0, %1, %2, %0;" : "+l"(acc[c][0]) : "l"(v64[0]),  "l"(wa.x));
                asm("fma.rn.f32x2 %0, %1, %2, %0;" : "+l"(acc[c][0]) : "l"(vs64[0]), "l"(wa.y));
                asm("fma.rn.f32x2 %0, %1, %2, %0;" : "+l"(acc[c][0]) : "l"(v64[1]),  "l"(wb.x));
                asm("fma.rn.f32x2 %0, %1, %2, %0;" : "+l"(acc[c][0]) : "l"(vs64[1]), "l"(wb.y));
                asm("fma.rn.f32x2 %0, %1, %2, %0;" : "+l"(acc[c][0]) : "l"(v64[2]),  "l"(wc.x));
                asm("fma.rn.f32x2 %0, %1, %2, %0;" : "+l"(acc[c][0]) : "l"(vs64[2]), "l"(wc.y));
                asm("fma.rn.f32x2 %0, %1, %2, %0;" : "+l"(acc[c][1]) : "l"(v64[1]),  "l"(wa.x));
                asm("fma.rn.f32x2 %0, %1, %2, %0;" : "+l"(acc[c][1]) : "l"(vs64[1]), "l"(wa.y));
                asm("fma.rn.f32x2 %0, %1, %2, %0;" : "+l"(acc[c][1]) : "l"(v64[2]),  "l"(wb.x));
                asm("fma.rn.f32x2 %0, %1, %2, %0;" : "+l"(acc[c][1]) : "l"(vs64[2]), "l"(wb.y));
                asm("fma.rn.f32x2 %0, %1, %2, %0;" : "+l"(acc[c][1]) : "l"(v64[3]),  "l"(wc.x));
                asm("fma.rn.f32x2 %0, %1, %2, %0;" : "+l"(acc[c][1]) : "l"(vs64[3]), "l"(wc.y));
            }
        }
    }

    // ---- data consistency + store (interleaved) ----
    const int ow = x0 + tx;
#pragma unroll
    for (int p = 0; p < 2; p++) {
        const int oh = y0 + row0 + p;
        const float m = g_bm[b*MHH*MWW + (oh % MHH)*MWW + (ow % MWW)];
        const bool keep = (m != 0.0f);
#pragma unroll
        for (int c = 0; c < 4; c++) {
            const int co = co0 + c;
            // at m==1 pred_prev == (masked) x; center value is in smem plane co
            ull v = keep ? s_in[co*PLANE2 + (row0 + p + 1)*35 + (tx + 1)]
                         : acc[c][p];
            dst[((b*NC + co)*HH + oh)*WW + ow] = v;
        }
        if (MASK_IN && cog == 0 && madj)
            madj[(b*HH + oh)*WW + ow] = m;
    }
}

// ---------------------------------------------------------------------------
extern "C" void kernel_launch(void* const* d_in, const int* in_sizes, int n_in,
                              void* d_out, int out_size) {
    const ull*   x     = (const ull*)d_in[0];     // [4,8,640,640] float2
    const float* my1   = (const float*)d_in[1];
    const float* wmask = (const float*)d_in[2];
    const float* wr    = (const float*)d_in[3];   // [4,8,8,3,3]
    const float* wi    = (const float*)d_in[4];
    float* out = (float*)d_out;

    void *pA, *pB, *pW;
    cudaGetSymbolAddress(&pA, g_bufA);
    cudaGetSymbolAddress(&pB, g_bufB);
    cudaGetSymbolAddress(&pW, g_wpack);
    ull* bufA = (ull*)pA;
    ull* bufB = (ull*)pB;

    const int PRED = NB*NC*HH*WW*2;
    const int MADJ = NB*HH*WW;
    const int BINM = NB*MHH*MWW;
    int has_extra = (out_size >= PRED + MADJ + BINM) ? 1 : 0;
    float* out_bin  = has_extra ? out + PRED + MADJ : nullptr;
    float* out_madj = has_extra ? out + PRED : nullptr;

    cudaFuncSetAttribute(conv_kernel<1>, cudaFuncAttributeMaxDynamicSharedMemorySize, SMEM_BYTES);
    cudaFuncSetAttribute(conv_kernel<0>, cudaFuncAttributeMaxDynamicSharedMemorySize, SMEM_BYTES);

    prep_weights<<<9, 256>>>(wr, wi);
    cudaMemcpyToSymbolAsync(c_wq, pW, 4*576*sizeof(ulonglong2), 0,
                            cudaMemcpyDeviceToDevice, 0);
    mask_kernel<<<NB, 256>>>(my1, wmask, out_bin, has_extra);

    dim3 grid(WW/TILE, HH/TILE, NB);  // 20 x 20 x 4
    conv_kernel<1><<<grid, 1024, SMEM_BYTES>>>(x,    bufA, out_madj, 0);
    conv_kernel<0><<<grid, 1024, SMEM_BYTES>>>(bufA, bufB, nullptr, 576);
    conv_kernel<0><<<grid, 1024, SMEM_BYTES>>>(bufB, bufA, nullptr, 1152);
    conv_kernel<0><<<grid, 1024, SMEM_BYTES>>>(bufA, (ull*)out, nullptr, 1728);
}

// round 11
// speedup vs baseline: 1.4011x; 1.4011x over previous
#include <cuda_runtime.h>
#include <math.h>

#define HH 640
#define WW 640
#define MHH 40
#define MWW 40
#define NC 8
#define NB 4
#define KPER 400

#define TILE 32
#define PLANE2 (34*35)                 // float2 units per plane
#define SMEM_BYTES (8*PLANE2*8)        // 76160: input planes only

typedef unsigned long long ull;

// scratch ping-pong buffers, interleaved float2 layout [b][c][H][W]
__device__ ull g_bufA[NB*NC*HH*WW];
__device__ ull g_bufB[NB*NC*HH*WW];
__device__ float g_bm[NB*MHH*MWW];
__device__ ulonglong2 g_wpack[4*576];     // packed weights staging

// weights in constant bank: [stage][((ci*3+kx)*8+co)*3+ky] = {wr,wr,-wi,wi}
__constant__ ulonglong2 c_wq[4*576];

// ---------------------------------------------------------------------------
// Pack weights: {wr, wr, -wi, wi} per (stage, ci, kx, co, ky), center zeroed.
// ---------------------------------------------------------------------------
__global__ void prep_weights(const float* __restrict__ wr_g,
                             const float* __restrict__ wi_g) {
    int j = blockIdx.x * blockDim.x + threadIdx.x;
    if (j >= 4*576) return;
    int s = j / 576, r = j % 576;
    int ky = r % 3, co = (r / 3) & 7, kx = (r / 24) % 3, ci = r / 72;
    int t = ky*3 + kx;
    float vr = 0.0f, vi = 0.0f;
    if (t != 4) {
        vr = wr_g[s*576 + (co*8 + ci)*9 + t];
        vi = wi_g[s*576 + (co*8 + ci)*9 + t];
    }
    float4 e; e.x = vr; e.y = vr; e.z = -vi; e.w = vi;
    ((float4*)g_wpack)[j] = e;
}

// ---------------------------------------------------------------------------
// Mask: sigmoid(s_b * w_eff), exact 400th-largest via binary search on float
// bits, binarize. One block per batch.
// ---------------------------------------------------------------------------
__global__ void mask_kernel(const float* __restrict__ my1,
                            const float* __restrict__ wmask,
                            float* __restrict__ out_bin, int write_bin) {
    __shared__ float s_sig[MHH*MWW];
    __shared__ int s_cnt;
    int b = blockIdx.x, tid = threadIdx.x;
    float sb = my1[b];
    for (int i = tid; i < MHH*MWW; i += blockDim.x) {
        int col = i % MWW;
        float wv = (col >= 18 && col < 23) ? 1e7f : wmask[i];
        s_sig[i] = 1.0f / (1.0f + expf(-sb * wv));
    }
    __syncthreads();
    unsigned lo = 0u, hi = 0x3F800001u;
    while (hi - lo > 1u) {
        unsigned mid = (lo + hi) >> 1;
        float t = __uint_as_float(mid);
        if (tid == 0) s_cnt = 0;
        __syncthreads();
        int c = 0;
        for (int i = tid; i < MHH*MWW; i += blockDim.x)
            c += (s_sig[i] >= t) ? 1 : 0;
        atomicAdd(&s_cnt, c);
        __syncthreads();
        int tot = s_cnt;
        __syncthreads();
        if (tot >= KPER) lo = mid; else hi = mid;
    }
    float thr = __uint_as_float(lo);
    for (int i = tid; i < MHH*MWW; i += blockDim.x) {
        float v = (s_sig[i] >= thr) ? 1.0f : 0.0f;
        g_bm[b*MHH*MWW + i] = v;
        if (write_bin) out_bin[b*MHH*MWW + i] = v;
    }
}

// ---------------------------------------------------------------------------
// Complex 3x3 conv (center zeroed) + data consistency.
// src/dst: interleaved float2 [b][c][H][W] (stored as ull).
// MASK_IN=1: src is raw x; zero where mask==0 on tile load; also writes
//            mask_adj to madj.
// 512 threads = 32 cols x 8 row-groups x 2 co-groups; 2 CTAs/SM (overlap!).
// Thread: 4 rows x 4 couts -> 32 acc regs, 288 LDC.128/thread.
// Math: acc{r,i} += v{r,i}*{wr,wr} + vswap{i,r}*{-wi,wi}   (2 FFMA2/tap)
// ---------------------------------------------------------------------------
template<int MASK_IN>
__global__ void __launch_bounds__(512, 2)
conv_kernel(const ull* __restrict__ src, ull* __restrict__ dst,
            float* __restrict__ madj, int stage_off) {
    extern __shared__ float smem[];
    ull* s_in = (ull*)smem;                 // 8 planes of 34x(35) float2

    const int tid = threadIdx.x;
    const int b  = blockIdx.z;
    const int x0 = blockIdx.x * TILE;
    const int y0 = blockIdx.y * TILE;

    // ---- load tile (halo 1, zero-padded) ----
    for (int idx = tid; idx < 34*34; idx += 512) {
        int r = idx / 34, c = idx - r*34;
        int gh = y0 - 1 + r, gw = x0 - 1 + c;
        bool inb = (gh >= 0 && gh < HH && gw >= 0 && gw < WW);
        bool live = inb;
        if (MASK_IN) {
            float m = 0.0f;
            if (inb) m = g_bm[b*MHH*MWW + (gh % MHH)*MWW + (gw % MWW)];
            live = inb && (m != 0.0f);
        }
#pragma unroll
        for (int ci = 0; ci < 8; ci++) {
            ull v = 0ull;
            if (live) v = src[((b*NC + ci)*HH + gh)*WW + gw];
            s_in[ci*PLANE2 + r*35 + c] = v;
        }
    }
    __syncthreads();

    const int tx   = tid & 31;
    const int ty   = tid >> 5;        // 0..15
    const int rowg = ty & 7;
    const int cog  = ty >> 3;
    const int row0 = rowg * 4;
    const int co0  = cog * 4;

    ull acc[4][4];                    // [cout][row], packed (accr, acci)
#pragma unroll
    for (int c = 0; c < 4; c++)
#pragma unroll
        for (int p = 0; p < 4; p++) acc[c][p] = 0ull;

#pragma unroll 1
    for (int ci = 0; ci < 8; ci++) {
        const ull* pb = s_in + ci*PLANE2 + row0*35 + tx;
#pragma unroll
        for (int kx = 0; kx < 3; kx++) {
            ull v64[6], vs64[6];
#pragma unroll
            for (int r = 0; r < 6; r++) {
                ull v = pb[r*35 + kx];
                v64[r] = v;
                float ar, ai;
                asm("mov.b64 {%0, %1}, %2;" : "=f"(ar), "=f"(ai) : "l"(v));
                asm("mov.b64 %0, {%1, %2};" : "=l"(vs64[r]) : "f"(ai), "f"(ar));
            }
            const int cb = stage_off + ((ci*3 + kx)*8 + co0)*3;
#pragma unroll
            for (int c = 0; c < 4; c++) {
                ulonglong2 wa = c_wq[cb + c*3 + 0];
                ulonglong2 wb = c_wq[cb + c*3 + 1];
                ulonglong2 wc = c_wq[cb + c*3 + 2];
#pragma unroll
                for (int p = 0; p < 4; p++) {
                    asm("fma.rn.f32x2 %0, %1, %2, %0;" : "+l"(acc[c][p]) : "l"(v64[p+0]),  "l"(wa.x));
                    asm("fma.rn.f32x2 %0, %1, %2, %0;" : "+l"(acc[c][p]) : "l"(vs64[p+0]), "l"(wa.y));
                    asm("fma.rn.f32x2 %0, %1, %2, %0;" : "+l"(acc[c][p]) : "l"(v64[p+1]),  "l"(wb.x));
                    asm("fma.rn.f32x2 %0, %1, %2, %0;" : "+l"(acc[c][p]) : "l"(vs64[p+1]), "l"(wb.y));
                    asm("fma.rn.f32x2 %0, %1, %2, %0;" : "+l"(acc[c][p]) : "l"(v64[p+2]),  "l"(wc.x));
                    asm("fma.rn.f32x2 %0, %1, %2, %0;" : "+l"(acc[c][p]) : "l"(vs64[p+2]), "l"(wc.y));
                }
            }
        }
    }

    // ---- data consistency + store (interleaved) ----
    const int ow = x0 + tx;
#pragma unroll
    for (int p = 0; p < 4; p++) {
        const int oh = y0 + row0 + p;
        const float m = g_bm[b*MHH*MWW + (oh % MHH)*MWW + (ow % MWW)];
        const bool keep = (m != 0.0f);
#pragma unroll
        for (int c = 0; c < 4; c++) {
            const int co = co0 + c;
            // at m==1 pred_prev == (masked) x; center value is in smem plane co
            ull v = keep ? s_in[co*PLANE2 + (row0 + p + 1)*35 + (tx + 1)]
                         : acc[c][p];
            dst[((b*NC + co)*HH + oh)*WW + ow] = v;
        }
        if (MASK_IN && cog == 0 && madj)
            madj[(b*HH + oh)*WW + ow] = m;
    }
}

// ---------------------------------------------------------------------------
extern "C" void kernel_launch(void* const* d_in, const int* in_sizes, int n_in,
                              void* d_out, int out_size) {
    const ull*   x     = (const ull*)d_in[0];     // [4,8,640,640] float2
    const float* my1   = (const float*)d_in[1];
    const float* wmask = (const float*)d_in[2];
    const float* wr    = (const float*)d_in[3];   // [4,8,8,3,3]
    const float* wi    = (const float*)d_in[4];
    float* out = (float*)d_out;

    void *pA, *pB, *pW;
    cudaGetSymbolAddress(&pA, g_bufA);
    cudaGetSymbolAddress(&pB, g_bufB);
    cudaGetSymbolAddress(&pW, g_wpack);
    ull* bufA = (ull*)pA;
    ull* bufB = (ull*)pB;

    const int PRED = NB*NC*HH*WW*2;
    const int MADJ = NB*HH*WW;
    const int BINM = NB*MHH*MWW;
    int has_extra = (out_size >= PRED + MADJ + BINM) ? 1 : 0;
    float* out_bin  = has_extra ? out + PRED + MADJ : nullptr;
    float* out_madj = has_extra ? out + PRED : nullptr;

    cudaFuncSetAttribute(conv_kernel<1>, cudaFuncAttributeMaxDynamicSharedMemorySize, SMEM_BYTES);
    cudaFuncSetAttribute(conv_kernel<0>, cudaFuncAttributeMaxDynamicSharedMemorySize, SMEM_BYTES);

    prep_weights<<<9, 256>>>(wr, wi);
    cudaMemcpyToSymbolAsync(c_wq, pW, 4*576*sizeof(ulonglong2), 0,
                            cudaMemcpyDeviceToDevice, 0);
    mask_kernel<<<NB, 256>>>(my1, wmask, out_bin, has_extra);

    dim3 grid(WW/TILE, HH/TILE, NB);  // 20 x 20 x 4
    conv_kernel<1><<<grid, 512, SMEM_BYTES>>>(x,    bufA, out_madj, 0);
    conv_kernel<0><<<grid, 512, SMEM_BYTES>>>(bufA, bufB, nullptr, 576);
    conv_kernel<0><<<grid, 512, SMEM_BYTES>>>(bufB, bufA, nullptr, 1152);
    conv_kernel<0><<<grid, 512, SMEM_BYTES>>>(bufA, (ull*)out, nullptr, 1728);
}

// round 12
// speedup vs baseline: 1.8532x; 1.3227x over previous
#include <cuda_runtime.h>
#include <math.h>

#define HH 640
#define WW 640
#define MHH 40
#define MWW 40
#define NC 8
#define NB 4
#define KPER 400

#define TILE 32
#define PLANE2 (34*35)                 // float2 units per plane
#define SMEM_BYTES (8*PLANE2*8)        // 76160: input planes only

typedef unsigned long long ull;

// scratch ping-pong buffers, interleaved float2 layout [b][c][H][W]
__device__ ull g_bufA[NB*NC*HH*WW];
__device__ ull g_bufB[NB*NC*HH*WW];
__device__ float g_bm[NB*MHH*MWW];
__device__ ulonglong2 g_wpack[4*576];     // packed weights staging

// weights in constant bank: [stage][((ci*3+kx)*8+co)*3+ky] = {wr,wr,-wi,wi}
__constant__ ulonglong2 c_wq[4*576];

// ---------------------------------------------------------------------------
// Pack weights: {wr, wr, -wi, wi} per (stage, ci, kx, co, ky), center zeroed.
// ---------------------------------------------------------------------------
__global__ void prep_weights(const float* __restrict__ wr_g,
                             const float* __restrict__ wi_g) {
    int j = blockIdx.x * blockDim.x + threadIdx.x;
    if (j >= 4*576) return;
    int s = j / 576, r = j % 576;
    int ky = r % 3, co = (r / 3) & 7, kx = (r / 24) % 3, ci = r / 72;
    int t = ky*3 + kx;
    float vr = 0.0f, vi = 0.0f;
    if (t != 4) {
        vr = wr_g[s*576 + (co*8 + ci)*9 + t];
        vi = wi_g[s*576 + (co*8 + ci)*9 + t];
    }
    float4 e; e.x = vr; e.y = vr; e.z = -vi; e.w = vi;
    ((float4*)g_wpack)[j] = e;
}

// ---------------------------------------------------------------------------
// Mask: sigmoid(s_b * w_eff), exact 400th-largest via binary search on float
// bits, binarize. One block per batch.
// ---------------------------------------------------------------------------
__global__ void mask_kernel(const float* __restrict__ my1,
                            const float* __restrict__ wmask,
                            float* __restrict__ out_bin, int write_bin) {
    __shared__ float s_sig[MHH*MWW];
    __shared__ int s_cnt;
    int b = blockIdx.x, tid = threadIdx.x;
    float sb = my1[b];
    for (int i = tid; i < MHH*MWW; i += blockDim.x) {
        int col = i % MWW;
        float wv = (col >= 18 && col < 23) ? 1e7f : wmask[i];
        s_sig[i] = 1.0f / (1.0f + expf(-sb * wv));
    }
    __syncthreads();
    unsigned lo = 0u, hi = 0x3F800001u;
    while (hi - lo > 1u) {
        unsigned mid = (lo + hi) >> 1;
        float t = __uint_as_float(mid);
        if (tid == 0) s_cnt = 0;
        __syncthreads();
        int c = 0;
        for (int i = tid; i < MHH*MWW; i += blockDim.x)
            c += (s_sig[i] >= t) ? 1 : 0;
        atomicAdd(&s_cnt, c);
        __syncthreads();
        int tot = s_cnt;
        __syncthreads();
        if (tot >= KPER) lo = mid; else hi = mid;
    }
    float thr = __uint_as_float(lo);
    for (int i = tid; i < MHH*MWW; i += blockDim.x) {
        float v = (s_sig[i] >= thr) ? 1.0f : 0.0f;
        g_bm[b*MHH*MWW + i] = v;
        if (write_bin) out_bin[b*MHH*MWW + i] = v;
    }
}

// ---------------------------------------------------------------------------
// Complex 3x3 conv (center zeroed) + data consistency.
// src/dst: interleaved float2 [b][c][H][W] (stored as ull).
// MASK_IN=1: src is raw x; zero where mask==0 on tile load; also writes
//            mask_adj to madj.
// 512 threads = 32 cols x 16 row-groups; thread: 2 rows x 8 couts (R7 shape:
// 56 regs, 2 CTAs/SM, FFMA2/LDC co-balanced, no spills).
// Math: acc{r,i} += v{r,i}*{wr,wr} + vswap{i,r}*{-wi,wi}   (2 FFMA2/tap)
// ---------------------------------------------------------------------------
template<int MASK_IN>
__global__ void __launch_bounds__(512, 2)
conv_kernel(const ull* __restrict__ src, ull* __restrict__ dst,
            float* __restrict__ madj, int stage_off) {
    extern __shared__ float smem[];
    ull* s_in = (ull*)smem;                 // 8 planes of 34x(35) float2

    const int tid = threadIdx.x;
    const int b  = blockIdx.z;
    const int x0 = blockIdx.x * TILE;
    const int y0 = blockIdx.y * TILE;

    // ---- load tile (halo 1, zero-padded) ----
    for (int idx = tid; idx < 34*34; idx += 512) {
        int r = idx / 34, c = idx - r*34;
        int gh = y0 - 1 + r, gw = x0 - 1 + c;
        bool inb = (gh >= 0 && gh < HH && gw >= 0 && gw < WW);
        bool live = inb;
        if (MASK_IN) {
            float m = 0.0f;
            if (inb) m = g_bm[b*MHH*MWW + (gh % MHH)*MWW + (gw % MWW)];
            live = inb && (m != 0.0f);
        }
#pragma unroll
        for (int ci = 0; ci < 8; ci++) {
            ull v = 0ull;
            if (live) v = src[((b*NC + ci)*HH + gh)*WW + gw];
            s_in[ci*PLANE2 + r*35 + c] = v;
        }
    }
    __syncthreads();

    const int tx = tid & 31, ty = tid >> 5;
    const int row0 = ty * 2;

    ull acc[8][2];
#pragma unroll
    for (int co = 0; co < 8; co++) { acc[co][0] = 0ull; acc[co][1] = 0ull; }

#pragma unroll 1
    for (int ci = 0; ci < 8; ci++) {
        const ull* pb = s_in + ci*PLANE2 + row0*35 + tx;
#pragma unroll
        for (int kx = 0; kx < 3; kx++) {
            ull v64[4], vs64[4];
#pragma unroll
            for (int r = 0; r < 4; r++) {
                ull v = pb[r*35 + kx];
                v64[r] = v;
                float ar, ai;
                asm("mov.b64 {%0, %1}, %2;" : "=f"(ar), "=f"(ai) : "l"(v));
                asm("mov.b64 %0, {%1, %2};" : "=l"(vs64[r]) : "f"(ai), "f"(ar));
            }
            const int cb = stage_off + ((ci*3 + kx)*8)*3;
#pragma unroll
            for (int co = 0; co < 8; co++) {
                ulonglong2 wa = c_wq[cb + co*3 + 0];
                ulonglong2 wb = c_wq[cb + co*3 + 1];
                ulonglong2 wc = c_wq[cb + co*3 + 2];
                asm("fma.rn.f32x2 %0, %1, %2, %0;" : "+l"(acc[co][0]) : "l"(v64[0]),  "l"(wa.x));
                asm("fma.rn.f32x2 %0, %1, %2, %0;" : "+l"(acc[co][0]) : "l"(vs64[0]), "l"(wa.y));
                asm("fma.rn.f32x2 %0, %1, %2, %0;" : "+l"(acc[co][0]) : "l"(v64[1]),  "l"(wb.x));
                asm("fma.rn.f32x2 %0, %1, %2, %0;" : "+l"(acc[co][0]) : "l"(vs64[1]), "l"(wb.y));
                asm("fma.rn.f32x2 %0, %1, %2, %0;" : "+l"(acc[co][0]) : "l"(v64[2]),  "l"(wc.x));
                asm("fma.rn.f32x2 %0, %1, %2, %0;" : "+l"(acc[co][0]) : "l"(vs64[2]), "l"(wc.y));
                asm("fma.rn.f32x2 %0, %1, %2, %0;" : "+l"(acc[co][1]) : "l"(v64[1]),  "l"(wa.x));
                asm("fma.rn.f32x2 %0, %1, %2, %0;" : "+l"(acc[co][1]) : "l"(vs64[1]), "l"(wa.y));
                asm("fma.rn.f32x2 %0, %1, %2, %0;" : "+l"(acc[co][1]) : "l"(v64[2]),  "l"(wb.x));
                asm("fma.rn.f32x2 %0, %1, %2, %0;" : "+l"(acc[co][1]) : "l"(vs64[2]), "l"(wb.y));
                asm("fma.rn.f32x2 %0, %1, %2, %0;" : "+l"(acc[co][1]) : "l"(v64[3]),  "l"(wc.x));
                asm("fma.rn.f32x2 %0, %1, %2, %0;" : "+l"(acc[co][1]) : "l"(vs64[3]), "l"(wc.y));
            }
        }
    }

    // ---- data consistency + store (interleaved) ----
    const int ow = x0 + tx;
#pragma unroll
    for (int p = 0; p < 2; p++) {
        const int oh = y0 + row0 + p;
        const float m = g_bm[b*MHH*MWW + (oh % MHH)*MWW + (ow % MWW)];
        const bool keep = (m != 0.0f);
#pragma unroll
        for (int co = 0; co < 8; co++) {
            // at m==1 pred_prev == (masked) x; center value is in smem plane co
            ull v = keep ? s_in[co*PLANE2 + (row0 + p + 1)*35 + (tx + 1)]
                         : acc[co][p];
            dst[((b*NC + co)*HH + oh)*WW + ow] = v;
        }
        if (MASK_IN && madj)
            madj[(b*HH + oh)*WW + ow] = m;
    }
}

// ---------------------------------------------------------------------------
extern "C" void kernel_launch(void* const* d_in, const int* in_sizes, int n_in,
                              void* d_out, int out_size) {
    const ull*   x     = (const ull*)d_in[0];     // [4,8,640,640] float2
    const float* my1   = (const float*)d_in[1];
    const float* wmask = (const float*)d_in[2];
    const float* wr    = (const float*)d_in[3];   // [4,8,8,3,3]
    const float* wi    = (const float*)d_in[4];
    float* out = (float*)d_out;

    void *pA, *pB, *pW;
    cudaGetSymbolAddress(&pA, g_bufA);
    cudaGetSymbolAddress(&pB, g_bufB);
    cudaGetSymbolAddress(&pW, g_wpack);
    ull* bufA = (ull*)pA;
    ull* bufB = (ull*)pB;

    const int PRED = NB*NC*HH*WW*2;
    const int MADJ = NB*HH*WW;
    const int BINM = NB*MHH*MWW;
    int has_extra = (out_size >= PRED + MADJ + BINM) ? 1 : 0;
    float* out_bin  = has_extra ? out + PRED + MADJ : nullptr;
    float* out_madj = has_extra ? out + PRED : nullptr;

    cudaFuncSetAttribute(conv_kernel<1>, cudaFuncAttributeMaxDynamicSharedMemorySize, SMEM_BYTES);
    cudaFuncSetAttribute(conv_kernel<0>, cudaFuncAttributeMaxDynamicSharedMemorySize, SMEM_BYTES);

    prep_weights<<<9, 256>>>(wr, wi);
    cudaMemcpyToSymbolAsync(c_wq, pW, 4*576*sizeof(ulonglong2), 0,
                            cudaMemcpyDeviceToDevice, 0);
    mask_kernel<<<NB, 256>>>(my1, wmask, out_bin, has_extra);

    dim3 grid(WW/TILE, HH/TILE, NB);  // 20 x 20 x 4
    conv_kernel<1><<<grid, 512, SMEM_BYTES>>>(x,    bufA, out_madj, 0);
    conv_kernel<0><<<grid, 512, SMEM_BYTES>>>(bufA, bufB, nullptr, 576);
    conv_kernel<0><<<grid, 512, SMEM_BYTES>>>(bufB, bufA, nullptr, 1152);
    conv_kernel<0><<<grid, 512, SMEM_BYTES>>>(bufA, (ull*)out, nullptr, 1728);
}

// round 13
// speedup vs baseline: 1.9927x; 1.0752x over previous
#include <cuda_runtime.h>
#include <math.h>

#define HH 640
#define WW 640
#define MHH 40
#define MWW 40
#define NC 8
#define NB 4
#define KPER 400

#define TILE 32
#define PLANE2 (34*35)                 // float2 units per plane
#define SMEM_BYTES (8*PLANE2*8)        // 76160: input planes only

typedef unsigned long long ull;

// scratch ping-pong buffers, interleaved float2 layout [b][c][H][W]
__device__ ull g_bufA[NB*NC*HH*WW];
__device__ ull g_bufB[NB*NC*HH*WW];
__device__ float g_bm[NB*MHH*MWW];
__device__ ulonglong2 g_wpack[4*576];     // packed weights staging

// weights in constant bank: [stage][((ci*3+kx)*8+co)*3+ky] = {wr,wr,-wi,wi}
__constant__ ulonglong2 c_wq[4*576];

// ---------------------------------------------------------------------------
// Pack weights: {wr, wr, -wi, wi} per (stage, ci, kx, co, ky), center zeroed.
// ---------------------------------------------------------------------------
__global__ void prep_weights(const float* __restrict__ wr_g,
                             const float* __restrict__ wi_g) {
    int j = blockIdx.x * blockDim.x + threadIdx.x;
    if (j >= 4*576) return;
    int s = j / 576, r = j % 576;
    int ky = r % 3, co = (r / 3) & 7, kx = (r / 24) % 3, ci = r / 72;
    int t = ky*3 + kx;
    float vr = 0.0f, vi = 0.0f;
    if (t != 4) {
        vr = wr_g[s*576 + (co*8 + ci)*9 + t];
        vi = wi_g[s*576 + (co*8 + ci)*9 + t];
    }
    float4 e; e.x = vr; e.y = vr; e.z = -vi; e.w = vi;
    ((float4*)g_wpack)[j] = e;
}

// ---------------------------------------------------------------------------
// Mask: sigmoid(s_b * w_eff), exact 400th-largest via binary search on float
// bits, binarize. One block per batch.
// ---------------------------------------------------------------------------
__global__ void mask_kernel(const float* __restrict__ my1,
                            const float* __restrict__ wmask,
                            float* __restrict__ out_bin, int write_bin) {
    __shared__ float s_sig[MHH*MWW];
    __shared__ int s_cnt;
    int b = blockIdx.x, tid = threadIdx.x;
    float sb = my1[b];
    for (int i = tid; i < MHH*MWW; i += blockDim.x) {
        int col = i % MWW;
        float wv = (col >= 18 && col < 23) ? 1e7f : wmask[i];
        s_sig[i] = 1.0f / (1.0f + expf(-sb * wv));
    }
    __syncthreads();
    unsigned lo = 0u, hi = 0x3F800001u;
    while (hi - lo > 1u) {
        unsigned mid = (lo + hi) >> 1;
        float t = __uint_as_float(mid);
        if (tid == 0) s_cnt = 0;
        __syncthreads();
        int c = 0;
        for (int i = tid; i < MHH*MWW; i += blockDim.x)
            c += (s_sig[i] >= t) ? 1 : 0;
        atomicAdd(&s_cnt, c);
        __syncthreads();
        int tot = s_cnt;
        __syncthreads();
        if (tot >= KPER) lo = mid; else hi = mid;
    }
    float thr = __uint_as_float(lo);
    for (int i = tid; i < MHH*MWW; i += blockDim.x) {
        float v = (s_sig[i] >= thr) ? 1.0f : 0.0f;
        g_bm[b*MHH*MWW + i] = v;
        if (write_bin) out_bin[b*MHH*MWW + i] = v;
    }
}

// ---------------------------------------------------------------------------
// Complex 3x3 conv (center zeroed) + data consistency.
// src/dst: interleaved float2 [b][c][H][W] (stored as ull).
// MASK_IN=1: src is raw x; zero where mask==0 on tile load; also writes
//            mask_adj to madj.
// 512 threads = 32 cols x 16 row-groups; thread: 2 rows x 8 couts.
// Center tap (kx=1, ky=1) is exactly zero -> its FFMA2s and LDCs are SKIPPED
// (2048 FFMA2 + 512 LDC.128 per thread instead of 2304 + 576).
// Math: acc{r,i} += v{r,i}*{wr,wr} + vswap{i,r}*{-wi,wi}   (2 FFMA2/tap)
// ---------------------------------------------------------------------------
template<int MASK_IN>
__global__ void __launch_bounds__(512, 2)
conv_kernel(const ull* __restrict__ src, ull* __restrict__ dst,
            float* __restrict__ madj, int stage_off) {
    extern __shared__ float smem[];
    ull* s_in = (ull*)smem;                 // 8 planes of 34x(35) float2

    const int tid = threadIdx.x;
    const int b  = blockIdx.z;
    const int x0 = blockIdx.x * TILE;
    const int y0 = blockIdx.y * TILE;

    // ---- load tile (halo 1, zero-padded) ----
    for (int idx = tid; idx < 34*34; idx += 512) {
        int r = idx / 34, c = idx - r*34;
        int gh = y0 - 1 + r, gw = x0 - 1 + c;
        bool inb = (gh >= 0 && gh < HH && gw >= 0 && gw < WW);
        bool live = inb;
        if (MASK_IN) {
            float m = 0.0f;
            if (inb) m = g_bm[b*MHH*MWW + (gh % MHH)*MWW + (gw % MWW)];
            live = inb && (m != 0.0f);
        }
#pragma unroll
        for (int ci = 0; ci < 8; ci++) {
            ull v = 0ull;
            if (live) v = src[((b*NC + ci)*HH + gh)*WW + gw];
            s_in[ci*PLANE2 + r*35 + c] = v;
        }
    }
    __syncthreads();

    const int tx = tid & 31, ty = tid >> 5;
    const int row0 = ty * 2;

    ull acc[8][2];
#pragma unroll
    for (int co = 0; co < 8; co++) { acc[co][0] = 0ull; acc[co][1] = 0ull; }

#pragma unroll 1
    for (int ci = 0; ci < 8; ci++) {
        const ull* pb = s_in + ci*PLANE2 + row0*35 + tx;
#pragma unroll
        for (int kx = 0; kx < 3; kx++) {
            ull v64[4], vs64[4];
#pragma unroll
            for (int r = 0; r < 4; r++) {
                ull v = pb[r*35 + kx];
                v64[r] = v;
                float ar, ai;
                asm("mov.b64 {%0, %1}, %2;" : "=f"(ar), "=f"(ai) : "l"(v));
                asm("mov.b64 %0, {%1, %2};" : "=l"(vs64[r]) : "f"(ai), "f"(ar));
            }
            const int cb = stage_off + ((ci*3 + kx)*8)*3;
#pragma unroll
            for (int co = 0; co < 8; co++) {
                ulonglong2 wa = c_wq[cb + co*3 + 0];
                ulonglong2 wc = c_wq[cb + co*3 + 2];
                asm("fma.rn.f32x2 %0, %1, %2, %0;" : "+l"(acc[co][0]) : "l"(v64[0]),  "l"(wa.x));
                asm("fma.rn.f32x2 %0, %1, %2, %0;" : "+l"(acc[co][0]) : "l"(vs64[0]), "l"(wa.y));
                asm("fma.rn.f32x2 %0, %1, %2, %0;" : "+l"(acc[co][0]) : "l"(v64[2]),  "l"(wc.x));
                asm("fma.rn.f32x2 %0, %1, %2, %0;" : "+l"(acc[co][0]) : "l"(vs64[2]), "l"(wc.y));
                asm("fma.rn.f32x2 %0, %1, %2, %0;" : "+l"(acc[co][1]) : "l"(v64[1]),  "l"(wa.x));
                asm("fma.rn.f32x2 %0, %1, %2, %0;" : "+l"(acc[co][1]) : "l"(vs64[1]), "l"(wa.y));
                asm("fma.rn.f32x2 %0, %1, %2, %0;" : "+l"(acc[co][1]) : "l"(v64[3]),  "l"(wc.x));
                asm("fma.rn.f32x2 %0, %1, %2, %0;" : "+l"(acc[co][1]) : "l"(vs64[3]), "l"(wc.y));
                if (kx != 1) {
                    // center tap (kx=1, ky=1) is exactly zero: skip wb there
                    ulonglong2 wb = c_wq[cb + co*3 + 1];
                    asm("fma.rn.f32x2 %0, %1, %2, %0;" : "+l"(acc[co][0]) : "l"(v64[1]),  "l"(wb.x));
                    asm("fma.rn.f32x2 %0, %1, %2, %0;" : "+l"(acc[co][0]) : "l"(vs64[1]), "l"(wb.y));
                    asm("fma.rn.f32x2 %0, %1, %2, %0;" : "+l"(acc[co][1]) : "l"(v64[2]),  "l"(wb.x));
                    asm("fma.rn.f32x2 %0, %1, %2, %0;" : "+l"(acc[co][1]) : "l"(vs64[2]), "l"(wb.y));
                }
            }
        }
    }

    // ---- data consistency + store (interleaved) ----
    const int ow = x0 + tx;
#pragma unroll
    for (int p = 0; p < 2; p++) {
        const int oh = y0 + row0 + p;
        const float m = g_bm[b*MHH*MWW + (oh % MHH)*MWW + (ow % MWW)];
        const bool keep = (m != 0.0f);
#pragma unroll
        for (int co = 0; co < 8; co++) {
            // at m==1 pred_prev == (masked) x; center value is in smem plane co
            ull v = keep ? s_in[co*PLANE2 + (row0 + p + 1)*35 + (tx + 1)]
                         : acc[co][p];
            dst[((b*NC + co)*HH + oh)*WW + ow] = v;
        }
        if (MASK_IN && madj)
            madj[(b*HH + oh)*WW + ow] = m;
    }
}

// ---------------------------------------------------------------------------
extern "C" void kernel_launch(void* const* d_in, const int* in_sizes, int n_in,
                              void* d_out, int out_size) {
    const ull*   x     = (const ull*)d_in[0];     // [4,8,640,640] float2
    const float* my1   = (const float*)d_in[1];
    const float* wmask = (const float*)d_in[2];
    const float* wr    = (const float*)d_in[3];   // [4,8,8,3,3]
    const float* wi    = (const float*)d_in[4];
    float* out = (float*)d_out;

    void *pA, *pB, *pW;
    cudaGetSymbolAddress(&pA, g_bufA);
    cudaGetSymbolAddress(&pB, g_bufB);
    cudaGetSymbolAddress(&pW, g_wpack);
    ull* bufA = (ull*)pA;
    ull* bufB = (ull*)pB;

    const int PRED = NB*NC*HH*WW*2;
    const int MADJ = NB*HH*WW;
    const int BINM = NB*MHH*MWW;
    int has_extra = (out_size >= PRED + MADJ + BINM) ? 1 : 0;
    float* out_bin  = has_extra ? out + PRED + MADJ : nullptr;
    float* out_madj = has_extra ? out + PRED : nullptr;

    cudaFuncSetAttribute(conv_kernel<1>, cudaFuncAttributeMaxDynamicSharedMemorySize, SMEM_BYTES);
    cudaFuncSetAttribute(conv_kernel<0>, cudaFuncAttributeMaxDynamicSharedMemorySize, SMEM_BYTES);

    prep_weights<<<9, 256>>>(wr, wi);
    cudaMemcpyToSymbolAsync(c_wq, pW, 4*576*sizeof(ulonglong2), 0,
                            cudaMemcpyDeviceToDevice, 0);
    mask_kernel<<<NB, 256>>>(my1, wmask, out_bin, has_extra);

    dim3 grid(WW/TILE, HH/TILE, NB);  // 20 x 20 x 4
    conv_kernel<1><<<grid, 512, SMEM_BYTES>>>(x,    bufA, out_madj, 0);
    conv_kernel<0><<<grid, 512, SMEM_BYTES>>>(bufA, bufB, nullptr, 576);
    conv_kernel<0><<<grid, 512, SMEM_BYTES>>>(bufB, bufA, nullptr, 1152);
    conv_kernel<0><<<grid, 512, SMEM_BYTES>>>(bufA, (ull*)out, nullptr, 1728);
}